// round 5
// baseline (speedup 1.0000x reference)
#include <cuda_runtime.h>
#include <cuda_bf16.h>
#include <cstdint>

// FA2-style mma.sync bf16 (3-term hi/lo split) flash attention.
// R5: fixes R4's double-offset STS bug. Double-buffered K/V with register
// prefetch, exp2-domain softmax with mask folded into bias table,
// dedicated mean(V) path for seq_len==0.

#define S_LEN 1024
#define BQ 128
#define BK 64
#define THREADS 256
#define LOG2E 1.44269504f
#define C2 13.0f

#define OFF_QHI 0
#define OFF_QLO 16384
#define BUF0 32768u
#define BUF1 65536u
#define KHI 0u
#define KLO 8192u
#define VHI 16384u
#define VLO 24576u
#define OFF_BIAS 98304
#define SMEM_TOTAL 102400

static __device__ __forceinline__ uint32_t smem_u32(const void* p) {
    uint32_t a;
    asm("{ .reg .u64 t; cvta.to.shared.u64 t, %1; cvt.u32.u64 %0, t; }" : "=r"(a) : "l"(p));
    return a;
}
static __device__ __forceinline__ void ldsm4(uint32_t addr, uint32_t& r0, uint32_t& r1,
                                             uint32_t& r2, uint32_t& r3) {
    asm volatile("ldmatrix.sync.aligned.m8n8.x4.shared.b16 {%0,%1,%2,%3}, [%4];"
                 : "=r"(r0), "=r"(r1), "=r"(r2), "=r"(r3) : "r"(addr));
}
static __device__ __forceinline__ void ldsm4t(uint32_t addr, uint32_t& r0, uint32_t& r1,
                                              uint32_t& r2, uint32_t& r3) {
    asm volatile("ldmatrix.sync.aligned.m8n8.x4.trans.shared.b16 {%0,%1,%2,%3}, [%4];"
                 : "=r"(r0), "=r"(r1), "=r"(r2), "=r"(r3) : "r"(addr));
}
static __device__ __forceinline__ void mma16816(float* c, uint32_t a0, uint32_t a1,
                                                uint32_t a2, uint32_t a3,
                                                uint32_t b0, uint32_t b1) {
    asm volatile("mma.sync.aligned.m16n8k16.row.col.f32.bf16.bf16.f32 "
                 "{%0,%1,%2,%3}, {%4,%5,%6,%7}, {%8,%9}, {%0,%1,%2,%3};"
                 : "+f"(c[0]), "+f"(c[1]), "+f"(c[2]), "+f"(c[3])
                 : "r"(a0), "r"(a1), "r"(a2), "r"(a3), "r"(b0), "r"(b1));
}
static __device__ __forceinline__ uint32_t pack_hi(float x, float y) {
    return __byte_perm(__float_as_uint(x), __float_as_uint(y), 0x7632);
}
static __device__ __forceinline__ uint32_t pack_lo(float x, float y) {
    float lx = x - __uint_as_float(__float_as_uint(x) & 0xffff0000u);
    float ly = y - __uint_as_float(__float_as_uint(y) & 0xffff0000u);
    uint32_t r;
    asm("cvt.rn.bf16x2.f32 %0, %1, %2;" : "=r"(r) : "f"(ly), "f"(lx));
    return r;
}

static __device__ __forceinline__ void ldg_tile(const float* base, int s0, int tid, float4* r) {
    #pragma unroll
    for (int i = 0; i < 4; i++) {
        int idx = tid + i * THREADS, row = idx >> 4, c4 = idx & 15;
        r[i] = *reinterpret_cast<const float4*>(base + (size_t)(s0 + row) * 2048 + c4 * 4);
    }
}
// NOTE: sm must be the smem BASE; hi_off/lo_off carry the full buffer offset.
static __device__ __forceinline__ void sts_tile(char* sm, uint32_t hi_off, uint32_t lo_off,
                                                int tid, const float4* r) {
    #pragma unroll
    for (int i = 0; i < 4; i++) {
        int idx = tid + i * THREADS, row = idx >> 4, c4 = idx & 15;
        uint32_t off = (uint32_t)(row * 128 + (((c4 >> 1) ^ (row & 7)) << 4) + ((c4 & 1) << 3));
        uint2 hi = { pack_hi(r[i].x, r[i].y), pack_hi(r[i].z, r[i].w) };
        uint2 lo = { pack_lo(r[i].x, r[i].y), pack_lo(r[i].z, r[i].w) };
        *reinterpret_cast<uint2*>(sm + hi_off + off) = hi;
        *reinterpret_cast<uint2*>(sm + lo_off + off) = lo;
    }
}

__global__ void __launch_bounds__(THREADS, 2)
attn_mma_kernel(const float* __restrict__ mem, const float* __restrict__ qry,
                const float* __restrict__ bias, const int* __restrict__ seqlen,
                float* __restrict__ out)
{
    extern __shared__ char smem[];
    const uint32_t sb = smem_u32(smem);
    const int tid = threadIdx.x, lane = tid & 31, wid = tid >> 5;
    const int qt = blockIdx.x, h = blockIdx.y, b = blockIdx.z;

    const int L = seqlen[b];
    const float* kbase = mem + (size_t)b * S_LEN * 2048 + h * 64;
    const float* vbase = kbase + 1024;
    float* obase0 = out + ((size_t)(b * S_LEN + qt * BQ)) * 1024 + h * 64;

    if (L == 0) {
        // softmax exactly uniform (fp32 rounding of -1e12): O = mean_k V
        float* red = reinterpret_cast<float*>(smem);
        int d = tid & 63, slc = tid >> 6;
        float s = 0.f;
        #pragma unroll 4
        for (int k = slc * 256; k < slc * 256 + 256; k++)
            s += vbase[(size_t)k * 2048 + d];
        red[slc * 64 + d] = s;
        __syncthreads();
        if (tid < 64)
            red[256 + tid] = (red[tid] + red[64 + tid] + red[128 + tid] + red[192 + tid])
                             * (1.f / 1024.f);
        __syncthreads();
        #pragma unroll
        for (int r = 0; r < 8; r++) {
            int idx = tid + r * THREADS;
            int row = idx >> 4, c4 = idx & 15;
            float4 vv = *reinterpret_cast<const float4*>(&red[256 + c4 * 4]);
            *reinterpret_cast<float4*>(obase0 + (size_t)row * 1024 + c4 * 4) = vv;
        }
        return;
    }

    float* Bs = reinterpret_cast<float*>(smem + OFF_BIAS);
    // bias in log2 domain, shift and MASK folded in (exp2(-1e30) == 0)
    #pragma unroll
    for (int i = tid; i < S_LEN; i += THREADS)
        Bs[i] = (i < L) ? bias[i] * LOG2E - C2 : -1e30f;

    // Q tile [128 x 64] scaled by (1/8)*log2e, hi/lo split, swizzled
    const float* qbase = qry + ((size_t)(b * S_LEN + qt * BQ)) * 1024 + h * 64;
    #pragma unroll
    for (int r = 0; r < 8; r++) {
        int idx = tid + r * THREADS;
        int row = idx >> 4, c4 = idx & 15;
        float4 v = *reinterpret_cast<const float4*>(qbase + (size_t)row * 1024 + c4 * 4);
        const float sc = 0.125f * LOG2E;
        v.x *= sc; v.y *= sc; v.z *= sc; v.w *= sc;
        uint32_t off = (uint32_t)(row * 128 + (((c4 >> 1) ^ (row & 7)) << 4) + ((c4 & 1) << 3));
        uint2 hi = { pack_hi(v.x, v.y), pack_hi(v.z, v.w) };
        uint2 lo = { pack_lo(v.x, v.y), pack_lo(v.z, v.w) };
        *reinterpret_cast<uint2*>(smem + OFF_QHI + off) = hi;
        *reinterpret_cast<uint2*>(smem + OFF_QLO + off) = lo;
    }

    const int nt = (L + BK - 1) >> 6;

    // lane geometry
    const int s7 = lane & 7;
    const int qA = (lane & 7) + ((lane >> 3) & 1) * 8;
    const int qB = lane >> 4;
    const int kA = (lane & 7) + (lane >> 4) * 8;
    const int kB = (lane >> 3) & 1;

    float oacc[8][4];
    #pragma unroll
    for (int i = 0; i < 8; i++)
        #pragma unroll
        for (int j = 0; j < 4; j++) oacc[i][j] = 0.f;
    float lsum0 = 0.f, lsum1 = 0.f;

    const uint32_t qrowb = sb + OFF_QHI + (uint32_t)(16 * wid + qA) * 128;

    // prologue: tile 0 -> BUF0
    {
        float4 kreg[4], vreg[4];
        ldg_tile(kbase, 0, tid, kreg);
        ldg_tile(vbase, 0, tid, vreg);
        sts_tile(smem, BUF0 + KHI, BUF0 + KLO, tid, kreg);
        sts_tile(smem, BUF0 + VHI, BUF0 + VLO, tid, vreg);
    }
    __syncthreads();

    for (int t = 0; t < nt; t++) {
        const int s0 = t * BK;
        const uint32_t kb = sb + ((t & 1) ? BUF1 : BUF0);
        const bool hn = (t + 1 < nt);
        float4 kreg[4], vreg[4];
        if (hn) ldg_tile(kbase, s0 + BK, tid, kreg);   // prefetch K(t+1)

        // ---- S = Q K^T (3-term split) ----
        float sacc[8][4];
        #pragma unroll
        for (int i = 0; i < 8; i++)
            #pragma unroll
            for (int j = 0; j < 4; j++) sacc[i][j] = 0.f;

        #pragma unroll
        for (int kk = 0; kk < 4; kk++) {
            uint32_t qh0, qh1, qh2, qh3, ql0, ql1, ql2, ql3;
            uint32_t aq = qrowb + (uint32_t)(((2 * kk + qB) ^ s7) << 4);
            ldsm4(aq, qh0, qh1, qh2, qh3);
            ldsm4(aq + (OFF_QLO - OFF_QHI), ql0, ql1, ql2, ql3);
            #pragma unroll
            for (int jj = 0; jj < 4; jj++) {
                uint32_t kh0, kh1, kh2, kh3, kl0, kl1, kl2, kl3;
                uint32_t ak = kb + KHI + (uint32_t)((16 * jj + kA) * 128 +
                              (((2 * kk + kB) ^ s7) << 4));
                ldsm4(ak, kh0, kh1, kh2, kh3);
                ldsm4(ak + 8192, kl0, kl1, kl2, kl3);
                mma16816(sacc[2 * jj],     qh0, qh1, qh2, qh3, kh0, kh1);
                mma16816(sacc[2 * jj + 1], qh0, qh1, qh2, qh3, kh2, kh3);
                mma16816(sacc[2 * jj],     qh0, qh1, qh2, qh3, kl0, kl1);
                mma16816(sacc[2 * jj + 1], qh0, qh1, qh2, qh3, kl2, kl3);
                mma16816(sacc[2 * jj],     ql0, ql1, ql2, ql3, kh0, kh1);
                mma16816(sacc[2 * jj + 1], ql0, ql1, ql2, ql3, kh2, kh3);
            }
        }

        if (hn) ldg_tile(vbase, s0 + BK, tid, vreg);   // prefetch V(t+1)

        // ---- softmax (exp2, mask pre-folded in Bs) + PV ----
        #pragma unroll
        for (int kk = 0; kk < 4; kk++) {
            uint32_t ph[4], pl[4];
            #pragma unroll
            for (int u = 0; u < 2; u++) {
                int j = 2 * kk + u;
                int keyb = s0 + 8 * j + 2 * (lane & 3);
                float2 bb = *reinterpret_cast<const float2*>(&Bs[keyb]);
                float p0 = exp2f(sacc[j][0] + bb.x);
                float p1 = exp2f(sacc[j][1] + bb.y);
                float p2 = exp2f(sacc[j][2] + bb.x);
                float p3 = exp2f(sacc[j][3] + bb.y);
                lsum0 += p0 + p1;
                lsum1 += p2 + p3;
                ph[2 * u]     = pack_hi(p0, p1);
                ph[2 * u + 1] = pack_hi(p2, p3);
                pl[2 * u]     = pack_lo(p0, p1);
                pl[2 * u + 1] = pack_lo(p2, p3);
            }
            #pragma unroll
            for (int jn = 0; jn < 4; jn++) {
                uint32_t vh0, vh1, vh2, vh3, vl0, vl1, vl2, vl3;
                uint32_t av = kb + VHI + (uint32_t)((16 * kk + qA) * 128 +
                              (((2 * jn + qB) ^ s7) << 4));
                ldsm4t(av, vh0, vh1, vh2, vh3);
                ldsm4t(av + 8192, vl0, vl1, vl2, vl3);
                mma16816(oacc[2 * jn],     ph[0], ph[1], ph[2], ph[3], vh0, vh1);
                mma16816(oacc[2 * jn + 1], ph[0], ph[1], ph[2], ph[3], vh2, vh3);
                mma16816(oacc[2 * jn],     pl[0], pl[1], pl[2], pl[3], vh0, vh1);
                mma16816(oacc[2 * jn + 1], pl[0], pl[1], pl[2], pl[3], vh2, vh3);
                mma16816(oacc[2 * jn],     ph[0], ph[1], ph[2], ph[3], vl0, vl1);
                mma16816(oacc[2 * jn + 1], ph[0], ph[1], ph[2], ph[3], vl2, vl3);
            }
        }

        if (hn) {
            const uint32_t nb = ((t + 1) & 1) ? BUF1 : BUF0;   // byte offset from smem base
            sts_tile(smem, nb + KHI, nb + KLO, tid, kreg);
            sts_tile(smem, nb + VHI, nb + VLO, tid, vreg);
        }
        __syncthreads();
    }

    // normalize within quads, store
    lsum0 += __shfl_xor_sync(0xffffffffu, lsum0, 1);
    lsum0 += __shfl_xor_sync(0xffffffffu, lsum0, 2);
    lsum1 += __shfl_xor_sync(0xffffffffu, lsum1, 1);
    lsum1 += __shfl_xor_sync(0xffffffffu, lsum1, 2);
    float inv0 = 1.f / lsum0, inv1 = 1.f / lsum1;

    const int r = lane >> 2, c2 = (lane & 3) * 2;
    float* ob = obase0 + (size_t)(16 * wid + r) * 1024;
    #pragma unroll
    for (int jd = 0; jd < 8; jd++) {
        float2 s0v = { oacc[jd][0] * inv0, oacc[jd][1] * inv0 };
        float2 s1v = { oacc[jd][2] * inv1, oacc[jd][3] * inv1 };
        *reinterpret_cast<float2*>(ob + 8 * jd + c2) = s0v;
        *reinterpret_cast<float2*>(ob + 8 * 1024 + 8 * jd + c2) = s1v;
    }
}

extern "C" void kernel_launch(void* const* d_in, const int* in_sizes, int n_in,
                              void* d_out, int out_size) {
    const float* mem  = (const float*)d_in[0];   // [8,1024,2048]
    const float* qry  = (const float*)d_in[1];   // [8,1024,1024]
    const float* bias = (const float*)d_in[2];   // [1024]
    const int*   sl   = (const int*)d_in[3];     // [8,1]
    float* out = (float*)d_out;

    cudaFuncSetAttribute(attn_mma_kernel, cudaFuncAttributeMaxDynamicSharedMemorySize, SMEM_TOTAL);
    dim3 grid(S_LEN / BQ, 16, 8);
    attn_mma_kernel<<<grid, THREADS, SMEM_TOTAL>>>(mem, qry, bias, sl, out);
}

// round 6
// speedup vs baseline: 1.3135x; 1.3135x over previous
#include <cuda_runtime.h>
#include <cuda_fp16.h>
#include <cstdint>

// FA2-style mma.sync FP16 flash attention (R6).
// 2-term splits: Q,P quantized once to fp16; K,V split exactly into fp16 hi+lo.
// QK = Q*Khi + Q*Klo ; PV = P*Vhi + P*Vlo  -> ~3e-4 rel err, 33% fewer MMAs
// than the 3-term bf16 version. Short-live-range prefetch; exp2-domain softmax
// with mask folded into bias table; mean(V) path for seq_len==0.

#define S_LEN 1024
#define BQ 128
#define BK 64
#define THREADS 256
#define LOG2E 1.44269504f
#define C2 13.0f

#define OFF_Q   0u
#define BUF0    16384u
#define BUF1    49152u
#define KHI     0u
#define KLO     8192u
#define VHI     16384u
#define VLO     24576u
#define OFF_BIAS 81920u
#define SMEM_TOTAL 86016

static __device__ __forceinline__ uint32_t smem_u32(const void* p) {
    uint32_t a;
    asm("{ .reg .u64 t; cvta.to.shared.u64 t, %1; cvt.u32.u64 %0, t; }" : "=r"(a) : "l"(p));
    return a;
}
static __device__ __forceinline__ void ldsm4(uint32_t addr, uint32_t& r0, uint32_t& r1,
                                             uint32_t& r2, uint32_t& r3) {
    asm volatile("ldmatrix.sync.aligned.m8n8.x4.shared.b16 {%0,%1,%2,%3}, [%4];"
                 : "=r"(r0), "=r"(r1), "=r"(r2), "=r"(r3) : "r"(addr));
}
static __device__ __forceinline__ void ldsm4t(uint32_t addr, uint32_t& r0, uint32_t& r1,
                                              uint32_t& r2, uint32_t& r3) {
    asm volatile("ldmatrix.sync.aligned.m8n8.x4.trans.shared.b16 {%0,%1,%2,%3}, [%4];"
                 : "=r"(r0), "=r"(r1), "=r"(r2), "=r"(r3) : "r"(addr));
}
static __device__ __forceinline__ void mma16816(float* c, uint32_t a0, uint32_t a1,
                                                uint32_t a2, uint32_t a3,
                                                uint32_t b0, uint32_t b1) {
    asm volatile("mma.sync.aligned.m16n8k16.row.col.f32.f16.f16.f32 "
                 "{%0,%1,%2,%3}, {%4,%5,%6,%7}, {%8,%9}, {%0,%1,%2,%3};"
                 : "+f"(c[0]), "+f"(c[1]), "+f"(c[2]), "+f"(c[3])
                 : "r"(a0), "r"(a1), "r"(a2), "r"(a3), "r"(b0), "r"(b1));
}
// pack: x -> low half, y -> high half (first cvt operand lands in the high half)
static __device__ __forceinline__ uint32_t pack_f16(float x, float y) {
    uint32_t r;
    asm("cvt.rn.f16x2.f32 %0, %1, %2;" : "=r"(r) : "f"(y), "f"(x));
    return r;
}

static __device__ __forceinline__ void ldg_tile(const float* base, int s0, int tid, float4* r) {
    #pragma unroll
    for (int i = 0; i < 4; i++) {
        int idx = tid + i * THREADS, row = idx >> 4, c4 = idx & 15;
        r[i] = *reinterpret_cast<const float4*>(base + (size_t)(s0 + row) * 2048 + c4 * 4);
    }
}
// K/V tile: fp16 hi (rn) + fp16 lo (exact residual), swizzled 128B rows
static __device__ __forceinline__ void sts_tile(char* sm, uint32_t hi_off, uint32_t lo_off,
                                                int tid, const float4* r) {
    #pragma unroll
    for (int i = 0; i < 4; i++) {
        int idx = tid + i * THREADS, row = idx >> 4, c4 = idx & 15;
        uint32_t off = (uint32_t)(row * 128 + (((c4 >> 1) ^ (row & 7)) << 4) + ((c4 & 1) << 3));
        float x = r[i].x, y = r[i].y, z = r[i].z, w = r[i].w;
        __half hx = __float2half_rn(x), hy = __float2half_rn(y);
        __half hz = __float2half_rn(z), hw = __float2half_rn(w);
        __half2 p0 = __halves2half2(hx, hy), p1 = __halves2half2(hz, hw);
        uint2 hi = { *reinterpret_cast<uint32_t*>(&p0), *reinterpret_cast<uint32_t*>(&p1) };
        uint2 lo = { pack_f16(x - __half2float(hx), y - __half2float(hy)),
                     pack_f16(z - __half2float(hz), w - __half2float(hw)) };
        *reinterpret_cast<uint2*>(sm + hi_off + off) = hi;
        *reinterpret_cast<uint2*>(sm + lo_off + off) = lo;
    }
}

__global__ void __launch_bounds__(THREADS, 2)
attn_mma_kernel(const float* __restrict__ mem, const float* __restrict__ qry,
                const float* __restrict__ bias, const int* __restrict__ seqlen,
                float* __restrict__ out)
{
    extern __shared__ char smem[];
    const uint32_t sb = smem_u32(smem);
    const int tid = threadIdx.x, lane = tid & 31, wid = tid >> 5;
    const int qt = blockIdx.x, h = blockIdx.y, b = blockIdx.z;

    const int L = seqlen[b];
    const float* kbase = mem + (size_t)b * S_LEN * 2048 + h * 64;
    const float* vbase = kbase + 1024;
    float* obase0 = out + ((size_t)(b * S_LEN + qt * BQ)) * 1024 + h * 64;

    if (L == 0) {
        // softmax exactly uniform (fp32 rounding of -1e12): O = mean_k V
        float* red = reinterpret_cast<float*>(smem);
        int d = tid & 63, slc = tid >> 6;
        float s = 0.f;
        #pragma unroll 4
        for (int k = slc * 256; k < slc * 256 + 256; k++)
            s += vbase[(size_t)k * 2048 + d];
        red[slc * 64 + d] = s;
        __syncthreads();
        if (tid < 64)
            red[256 + tid] = (red[tid] + red[64 + tid] + red[128 + tid] + red[192 + tid])
                             * (1.f / 1024.f);
        __syncthreads();
        #pragma unroll
        for (int r = 0; r < 8; r++) {
            int idx = tid + r * THREADS;
            int row = idx >> 4, c4 = idx & 15;
            float4 vv = *reinterpret_cast<const float4*>(&red[256 + c4 * 4]);
            *reinterpret_cast<float4*>(obase0 + (size_t)row * 1024 + c4 * 4) = vv;
        }
        return;
    }

    float* Bs = reinterpret_cast<float*>(smem + OFF_BIAS);
    // bias in log2 domain, shift and MASK folded in (exp2(-1e30) == 0)
    #pragma unroll
    for (int i = tid; i < S_LEN; i += THREADS)
        Bs[i] = (i < L) ? bias[i] * LOG2E - C2 : -1e30f;

    // Q tile [128 x 64] scaled by (1/8)*log2e, single fp16, swizzled
    const float* qbase = qry + ((size_t)(b * S_LEN + qt * BQ)) * 1024 + h * 64;
    #pragma unroll
    for (int r = 0; r < 8; r++) {
        int idx = tid + r * THREADS;
        int row = idx >> 4, c4 = idx & 15;
        float4 v = *reinterpret_cast<const float4*>(qbase + (size_t)row * 1024 + c4 * 4);
        const float sc = 0.125f * LOG2E;
        uint32_t off = (uint32_t)(row * 128 + (((c4 >> 1) ^ (row & 7)) << 4) + ((c4 & 1) << 3));
        uint2 q16 = { pack_f16(v.x * sc, v.y * sc), pack_f16(v.z * sc, v.w * sc) };
        *reinterpret_cast<uint2*>(smem + OFF_Q + off) = q16;
    }

    const int nt = (L + BK - 1) >> 6;

    // lane geometry
    const int s7 = lane & 7;
    const int qA = (lane & 7) + ((lane >> 3) & 1) * 8;
    const int qB = lane >> 4;
    const int kA = (lane & 7) + (lane >> 4) * 8;
    const int kB = (lane >> 3) & 1;

    float oacc[8][4];
    #pragma unroll
    for (int i = 0; i < 8; i++)
        #pragma unroll
        for (int j = 0; j < 4; j++) oacc[i][j] = 0.f;
    float lsum0 = 0.f, lsum1 = 0.f;

    const uint32_t qrowb = sb + OFF_Q + (uint32_t)(16 * wid + qA) * 128;

    // prologue: tile 0 -> BUF0
    {
        float4 kreg[4], vreg[4];
        ldg_tile(kbase, 0, tid, kreg);
        ldg_tile(vbase, 0, tid, vreg);
        sts_tile(smem, BUF0 + KHI, BUF0 + KLO, tid, kreg);
        sts_tile(smem, BUF0 + VHI, BUF0 + VLO, tid, vreg);
    }
    __syncthreads();

    for (int t = 0; t < nt; t++) {
        const int s0 = t * BK;
        const uint32_t kb = sb + ((t & 1) ? BUF1 : BUF0);
        const uint32_t nb = ((t + 1) & 1) ? BUF1 : BUF0;   // byte offset of next buffer
        const bool hn = (t + 1 < nt);

        {
            float4 kreg[4];
            if (hn) ldg_tile(kbase, s0 + BK, tid, kreg);   // prefetch K(t+1)

            // ---- S = Q*Khi + Q*Klo ----
            float sacc[8][4];
            #pragma unroll
            for (int i = 0; i < 8; i++)
                #pragma unroll
                for (int j = 0; j < 4; j++) sacc[i][j] = 0.f;

            #pragma unroll
            for (int kk = 0; kk < 4; kk++) {
                uint32_t q0, q1, q2, q3;
                ldsm4(qrowb + (uint32_t)(((2 * kk + qB) ^ s7) << 4), q0, q1, q2, q3);
                #pragma unroll
                for (int jj = 0; jj < 4; jj++) {
                    uint32_t kh0, kh1, kh2, kh3, kl0, kl1, kl2, kl3;
                    uint32_t ak = kb + KHI + (uint32_t)((16 * jj + kA) * 128 +
                                  (((2 * kk + kB) ^ s7) << 4));
                    ldsm4(ak, kh0, kh1, kh2, kh3);
                    ldsm4(ak + 8192, kl0, kl1, kl2, kl3);
                    mma16816(sacc[2 * jj],     q0, q1, q2, q3, kh0, kh1);
                    mma16816(sacc[2 * jj + 1], q0, q1, q2, q3, kh2, kh3);
                    mma16816(sacc[2 * jj],     q0, q1, q2, q3, kl0, kl1);
                    mma16816(sacc[2 * jj + 1], q0, q1, q2, q3, kl2, kl3);
                }
            }

            if (hn) sts_tile(smem, nb + KHI, nb + KLO, tid, kreg);  // kreg dies here

            // ---- softmax (exp2, mask pre-folded) -> P fp16 fragments, saved per kk ----
            #pragma unroll
            for (int kk = 0; kk < 4; kk++) {
                #pragma unroll
                for (int u = 0; u < 2; u++) {
                    int j = 2 * kk + u;
                    int keyb = s0 + 8 * j + 2 * (lane & 3);
                    float2 bb = *reinterpret_cast<const float2*>(&Bs[keyb]);
                    float p0 = exp2f(sacc[j][0] + bb.x);
                    float p1 = exp2f(sacc[j][1] + bb.y);
                    float p2 = exp2f(sacc[j][2] + bb.x);
                    float p3 = exp2f(sacc[j][3] + bb.y);
                    lsum0 += p0 + p1;
                    lsum1 += p2 + p3;
                    sacc[j][0] = __uint_as_float(pack_f16(p0, p1));   // reuse sacc as P store
                    sacc[j][1] = __uint_as_float(pack_f16(p2, p3));
                }
            }

            float4 vreg[4];
            if (hn) ldg_tile(vbase, s0 + BK, tid, vreg);   // prefetch V(t+1)

            // ---- O += P*Vhi + P*Vlo ----
            #pragma unroll
            for (int kk = 0; kk < 4; kk++) {
                uint32_t ph0 = __float_as_uint(sacc[2 * kk][0]);
                uint32_t ph1 = __float_as_uint(sacc[2 * kk][1]);
                uint32_t ph2 = __float_as_uint(sacc[2 * kk + 1][0]);
                uint32_t ph3 = __float_as_uint(sacc[2 * kk + 1][1]);
                #pragma unroll
                for (int jn = 0; jn < 4; jn++) {
                    uint32_t vh0, vh1, vh2, vh3, vl0, vl1, vl2, vl3;
                    uint32_t av = kb + VHI + (uint32_t)((16 * kk + qA) * 128 +
                                  (((2 * jn + qB) ^ s7) << 4));
                    ldsm4t(av, vh0, vh1, vh2, vh3);
                    ldsm4t(av + 8192, vl0, vl1, vl2, vl3);
                    mma16816(oacc[2 * jn],     ph0, ph1, ph2, ph3, vh0, vh1);
                    mma16816(oacc[2 * jn + 1], ph0, ph1, ph2, ph3, vh2, vh3);
                    mma16816(oacc[2 * jn],     ph0, ph1, ph2, ph3, vl0, vl1);
                    mma16816(oacc[2 * jn + 1], ph0, ph1, ph2, ph3, vl2, vl3);
                }
            }

            if (hn) sts_tile(smem, nb + VHI, nb + VLO, tid, vreg);
        }
        __syncthreads();
    }

    // normalize within quads, store
    lsum0 += __shfl_xor_sync(0xffffffffu, lsum0, 1);
    lsum0 += __shfl_xor_sync(0xffffffffu, lsum0, 2);
    lsum1 += __shfl_xor_sync(0xffffffffu, lsum1, 1);
    lsum1 += __shfl_xor_sync(0xffffffffu, lsum1, 2);
    float inv0 = 1.f / lsum0, inv1 = 1.f / lsum1;

    const int r = lane >> 2, c2 = (lane & 3) * 2;
    float* ob = obase0 + (size_t)(16 * wid + r) * 1024;
    #pragma unroll
    for (int jd = 0; jd < 8; jd++) {
        float2 s0v = { oacc[jd][0] * inv0, oacc[jd][1] * inv0 };
        float2 s1v = { oacc[jd][2] * inv1, oacc[jd][3] * inv1 };
        *reinterpret_cast<float2*>(ob + 8 * jd + c2) = s0v;
        *reinterpret_cast<float2*>(ob + 8 * 1024 + 8 * jd + c2) = s1v;
    }
}

extern "C" void kernel_launch(void* const* d_in, const int* in_sizes, int n_in,
                              void* d_out, int out_size) {
    const float* mem  = (const float*)d_in[0];   // [8,1024,2048]
    const float* qry  = (const float*)d_in[1];   // [8,1024,1024]
    const float* bias = (const float*)d_in[2];   // [1024]
    const int*   sl   = (const int*)d_in[3];     // [8,1]
    float* out = (float*)d_out;

    cudaFuncSetAttribute(attn_mma_kernel, cudaFuncAttributeMaxDynamicSharedMemorySize, SMEM_TOTAL);
    dim3 grid(S_LEN / BQ, 16, 8);
    attn_mma_kernel<<<grid, THREADS, SMEM_TOTAL>>>(mem, qry, bias, sl, out);
}

// round 7
// speedup vs baseline: 1.5824x; 1.2047x over previous
#include <cuda_runtime.h>
#include <cuda_fp16.h>
#include <cstdint>

// FA2-style mma.sync FP16 flash attention (R7).
// Q,P fp16-rn; K split fp16 hi+lo (2-term QK); V fp16-rn single term PV
// (V error averages down linearly in O; ~4.5e-4 total rel err).
// Short-live-range prefetch; exp2 softmax, mask folded into bias; mean(V)
// fast path for seq_len==0.

#define S_LEN 1024
#define BQ 128
#define BK 64
#define THREADS 256
#define LOG2E 1.44269504f
#define C2 13.0f

#define OFF_Q   0u
#define BUF0    16384u
#define BUF1    40960u
#define KHI     0u
#define KLO     8192u
#define VHI     16384u
#define OFF_BIAS 65536u
#define SMEM_TOTAL 69632

static __device__ __forceinline__ uint32_t smem_u32(const void* p) {
    uint32_t a;
    asm("{ .reg .u64 t; cvta.to.shared.u64 t, %1; cvt.u32.u64 %0, t; }" : "=r"(a) : "l"(p));
    return a;
}
static __device__ __forceinline__ void ldsm4(uint32_t addr, uint32_t& r0, uint32_t& r1,
                                             uint32_t& r2, uint32_t& r3) {
    asm volatile("ldmatrix.sync.aligned.m8n8.x4.shared.b16 {%0,%1,%2,%3}, [%4];"
                 : "=r"(r0), "=r"(r1), "=r"(r2), "=r"(r3) : "r"(addr));
}
static __device__ __forceinline__ void ldsm4t(uint32_t addr, uint32_t& r0, uint32_t& r1,
                                              uint32_t& r2, uint32_t& r3) {
    asm volatile("ldmatrix.sync.aligned.m8n8.x4.trans.shared.b16 {%0,%1,%2,%3}, [%4];"
                 : "=r"(r0), "=r"(r1), "=r"(r2), "=r"(r3) : "r"(addr));
}
static __device__ __forceinline__ void mma16816(float* c, uint32_t a0, uint32_t a1,
                                                uint32_t a2, uint32_t a3,
                                                uint32_t b0, uint32_t b1) {
    asm volatile("mma.sync.aligned.m16n8k16.row.col.f32.f16.f16.f32 "
                 "{%0,%1,%2,%3}, {%4,%5,%6,%7}, {%8,%9}, {%0,%1,%2,%3};"
                 : "+f"(c[0]), "+f"(c[1]), "+f"(c[2]), "+f"(c[3])
                 : "r"(a0), "r"(a1), "r"(a2), "r"(a3), "r"(b0), "r"(b1));
}
// pack: x -> low half, y -> high half
static __device__ __forceinline__ uint32_t pack_f16(float x, float y) {
    uint32_t r;
    asm("cvt.rn.f16x2.f32 %0, %1, %2;" : "=r"(r) : "f"(y), "f"(x));
    return r;
}

static __device__ __forceinline__ void ldg_tile(const float* base, int s0, int tid, float4* r) {
    #pragma unroll
    for (int i = 0; i < 4; i++) {
        int idx = tid + i * THREADS, row = idx >> 4, c4 = idx & 15;
        r[i] = *reinterpret_cast<const float4*>(base + (size_t)(s0 + row) * 2048 + c4 * 4);
    }
}
// K tile: fp16 hi (rn) + fp16 lo (residual), swizzled 128B rows
static __device__ __forceinline__ void sts_tile_k(char* sm, uint32_t hi_off, uint32_t lo_off,
                                                  int tid, const float4* r) {
    #pragma unroll
    for (int i = 0; i < 4; i++) {
        int idx = tid + i * THREADS, row = idx >> 4, c4 = idx & 15;
        uint32_t off = (uint32_t)(row * 128 + (((c4 >> 1) ^ (row & 7)) << 4) + ((c4 & 1) << 3));
        float x = r[i].x, y = r[i].y, z = r[i].z, w = r[i].w;
        __half hx = __float2half_rn(x), hy = __float2half_rn(y);
        __half hz = __float2half_rn(z), hw = __float2half_rn(w);
        __half2 p0 = __halves2half2(hx, hy), p1 = __halves2half2(hz, hw);
        uint2 hi = { *reinterpret_cast<uint32_t*>(&p0), *reinterpret_cast<uint32_t*>(&p1) };
        uint2 lo = { pack_f16(x - __half2float(hx), y - __half2float(hy)),
                     pack_f16(z - __half2float(hz), w - __half2float(hw)) };
        *reinterpret_cast<uint2*>(sm + hi_off + off) = hi;
        *reinterpret_cast<uint2*>(sm + lo_off + off) = lo;
    }
}
// V tile: fp16 rn only
static __device__ __forceinline__ void sts_tile_v(char* sm, uint32_t v_off,
                                                  int tid, const float4* r) {
    #pragma unroll
    for (int i = 0; i < 4; i++) {
        int idx = tid + i * THREADS, row = idx >> 4, c4 = idx & 15;
        uint32_t off = (uint32_t)(row * 128 + (((c4 >> 1) ^ (row & 7)) << 4) + ((c4 & 1) << 3));
        uint2 hv = { pack_f16(r[i].x, r[i].y), pack_f16(r[i].z, r[i].w) };
        *reinterpret_cast<uint2*>(sm + v_off + off) = hv;
    }
}

__global__ void __launch_bounds__(THREADS, 2)
attn_mma_kernel(const float* __restrict__ mem, const float* __restrict__ qry,
                const float* __restrict__ bias, const int* __restrict__ seqlen,
                float* __restrict__ out)
{
    extern __shared__ char smem[];
    const uint32_t sb = smem_u32(smem);
    const int tid = threadIdx.x, lane = tid & 31, wid = tid >> 5;
    const int qt = blockIdx.x, h = blockIdx.y, b = blockIdx.z;

    const int L = seqlen[b];
    const float* kbase = mem + (size_t)b * S_LEN * 2048 + h * 64;
    const float* vbase = kbase + 1024;
    float* obase0 = out + ((size_t)(b * S_LEN + qt * BQ)) * 1024 + h * 64;

    if (L == 0) {
        // softmax exactly uniform (fp32 rounding of -1e12): O = mean_k V
        float* red = reinterpret_cast<float*>(smem);
        int d = tid & 63, slc = tid >> 6;
        float s = 0.f;
        #pragma unroll 4
        for (int k = slc * 256; k < slc * 256 + 256; k++)
            s += vbase[(size_t)k * 2048 + d];
        red[slc * 64 + d] = s;
        __syncthreads();
        if (tid < 64)
            red[256 + tid] = (red[tid] + red[64 + tid] + red[128 + tid] + red[192 + tid])
                             * (1.f / 1024.f);
        __syncthreads();
        #pragma unroll
        for (int r = 0; r < 8; r++) {
            int idx = tid + r * THREADS;
            int row = idx >> 4, c4 = idx & 15;
            float4 vv = *reinterpret_cast<const float4*>(&red[256 + c4 * 4]);
            *reinterpret_cast<float4*>(obase0 + (size_t)row * 1024 + c4 * 4) = vv;
        }
        return;
    }

    float* Bs = reinterpret_cast<float*>(smem + OFF_BIAS);
    // bias in log2 domain, shift and MASK folded in (exp2(-1e30) == 0)
    #pragma unroll
    for (int i = tid; i < S_LEN; i += THREADS)
        Bs[i] = (i < L) ? bias[i] * LOG2E - C2 : -1e30f;

    // Q tile [128 x 64] scaled by (1/8)*log2e, fp16, swizzled
    const float* qbase = qry + ((size_t)(b * S_LEN + qt * BQ)) * 1024 + h * 64;
    #pragma unroll
    for (int r = 0; r < 8; r++) {
        int idx = tid + r * THREADS;
        int row = idx >> 4, c4 = idx & 15;
        float4 v = *reinterpret_cast<const float4*>(qbase + (size_t)row * 1024 + c4 * 4);
        const float sc = 0.125f * LOG2E;
        uint32_t off = (uint32_t)(row * 128 + (((c4 >> 1) ^ (row & 7)) << 4) + ((c4 & 1) << 3));
        uint2 q16 = { pack_f16(v.x * sc, v.y * sc), pack_f16(v.z * sc, v.w * sc) };
        *reinterpret_cast<uint2*>(smem + OFF_Q + off) = q16;
    }

    const int nt = (L + BK - 1) >> 6;

    // lane geometry
    const int s7 = lane & 7;
    const int qA = (lane & 7) + ((lane >> 3) & 1) * 8;
    const int qB = lane >> 4;
    const int kA = (lane & 7) + (lane >> 4) * 8;
    const int kB = (lane >> 3) & 1;

    float oacc[8][4];
    #pragma unroll
    for (int i = 0; i < 8; i++)
        #pragma unroll
        for (int j = 0; j < 4; j++) oacc[i][j] = 0.f;
    float lsum0 = 0.f, lsum1 = 0.f;

    const uint32_t qrowb = sb + OFF_Q + (uint32_t)(16 * wid + qA) * 128;

    // prologue: tile 0 -> BUF0
    {
        float4 kreg[4], vreg[4];
        ldg_tile(kbase, 0, tid, kreg);
        ldg_tile(vbase, 0, tid, vreg);
        sts_tile_k(smem, BUF0 + KHI, BUF0 + KLO, tid, kreg);
        sts_tile_v(smem, BUF0 + VHI, tid, vreg);
    }
    __syncthreads();

    for (int t = 0; t < nt; t++) {
        const int s0 = t * BK;
        const uint32_t kb = sb + ((t & 1) ? BUF1 : BUF0);
        const uint32_t nb = ((t + 1) & 1) ? BUF1 : BUF0;   // next buffer byte offset
        const bool hn = (t + 1 < nt);

        {
            float4 kreg[4];
            if (hn) ldg_tile(kbase, s0 + BK, tid, kreg);   // prefetch K(t+1)

            // ---- S = Q*Khi + Q*Klo ----
            float sacc[8][4];
            #pragma unroll
            for (int i = 0; i < 8; i++)
                #pragma unroll
                for (int j = 0; j < 4; j++) sacc[i][j] = 0.f;

            #pragma unroll
            for (int kk = 0; kk < 4; kk++) {
                uint32_t q0, q1, q2, q3;
                ldsm4(qrowb + (uint32_t)(((2 * kk + qB) ^ s7) << 4), q0, q1, q2, q3);
                #pragma unroll
                for (int jj = 0; jj < 4; jj++) {
                    uint32_t kh0, kh1, kh2, kh3, kl0, kl1, kl2, kl3;
                    uint32_t ak = kb + KHI + (uint32_t)((16 * jj + kA) * 128 +
                                  (((2 * kk + kB) ^ s7) << 4));
                    ldsm4(ak, kh0, kh1, kh2, kh3);
                    ldsm4(ak + 8192, kl0, kl1, kl2, kl3);
                    mma16816(sacc[2 * jj],     q0, q1, q2, q3, kh0, kh1);
                    mma16816(sacc[2 * jj + 1], q0, q1, q2, q3, kh2, kh3);
                    mma16816(sacc[2 * jj],     q0, q1, q2, q3, kl0, kl1);
                    mma16816(sacc[2 * jj + 1], q0, q1, q2, q3, kl2, kl3);
                }
            }

            if (hn) sts_tile_k(smem, nb + KHI, nb + KLO, tid, kreg);  // kreg dies here

            // ---- softmax (exp2, mask pre-folded) -> P fp16 fragments in sacc ----
            #pragma unroll
            for (int kk = 0; kk < 4; kk++) {
                #pragma unroll
                for (int u = 0; u < 2; u++) {
                    int j = 2 * kk + u;
                    int keyb = s0 + 8 * j + 2 * (lane & 3);
                    float2 bb = *reinterpret_cast<const float2*>(&Bs[keyb]);
                    float p0 = exp2f(sacc[j][0] + bb.x);
                    float p1 = exp2f(sacc[j][1] + bb.y);
                    float p2 = exp2f(sacc[j][2] + bb.x);
                    float p3 = exp2f(sacc[j][3] + bb.y);
                    lsum0 += p0 + p1;
                    lsum1 += p2 + p3;
                    sacc[j][0] = __uint_as_float(pack_f16(p0, p1));
                    sacc[j][1] = __uint_as_float(pack_f16(p2, p3));
                }
            }

            float4 vreg[4];
            if (hn) ldg_tile(vbase, s0 + BK, tid, vreg);   // prefetch V(t+1)

            // ---- O += P*V (single fp16 term) ----
            #pragma unroll
            for (int kk = 0; kk < 4; kk++) {
                uint32_t ph0 = __float_as_uint(sacc[2 * kk][0]);
                uint32_t ph1 = __float_as_uint(sacc[2 * kk][1]);
                uint32_t ph2 = __float_as_uint(sacc[2 * kk + 1][0]);
                uint32_t ph3 = __float_as_uint(sacc[2 * kk + 1][1]);
                #pragma unroll
                for (int jn = 0; jn < 4; jn++) {
                    uint32_t vh0, vh1, vh2, vh3;
                    uint32_t av = kb + VHI + (uint32_t)((16 * kk + qA) * 128 +
                                  (((2 * jn + qB) ^ s7) << 4));
                    ldsm4t(av, vh0, vh1, vh2, vh3);
                    mma16816(oacc[2 * jn],     ph0, ph1, ph2, ph3, vh0, vh1);
                    mma16816(oacc[2 * jn + 1], ph0, ph1, ph2, ph3, vh2, vh3);
                }
            }

            if (hn) sts_tile_v(smem, nb + VHI, tid, vreg);
        }
        __syncthreads();
    }

    // normalize within quads, store
    lsum0 += __shfl_xor_sync(0xffffffffu, lsum0, 1);
    lsum0 += __shfl_xor_sync(0xffffffffu, lsum0, 2);
    lsum1 += __shfl_xor_sync(0xffffffffu, lsum1, 1);
    lsum1 += __shfl_xor_sync(0xffffffffu, lsum1, 2);
    float inv0 = 1.f / lsum0, inv1 = 1.f / lsum1;

    const int r = lane >> 2, c2 = (lane & 3) * 2;
    float* ob = obase0 + (size_t)(16 * wid + r) * 1024;
    #pragma unroll
    for (int jd = 0; jd < 8; jd++) {
        float2 s0v = { oacc[jd][0] * inv0, oacc[jd][1] * inv0 };
        float2 s1v = { oacc[jd][2] * inv1, oacc[jd][3] * inv1 };
        *reinterpret_cast<float2*>(ob + 8 * jd + c2) = s0v;
        *reinterpret_cast<float2*>(ob + 8 * 1024 + 8 * jd + c2) = s1v;
    }
}

extern "C" void kernel_launch(void* const* d_in, const int* in_sizes, int n_in,
                              void* d_out, int out_size) {
    const float* mem  = (const float*)d_in[0];   // [8,1024,2048]
    const float* qry  = (const float*)d_in[1];   // [8,1024,1024]
    const float* bias = (const float*)d_in[2];   // [1024]
    const int*   sl   = (const int*)d_in[3];     // [8,1]
    float* out = (float*)d_out;

    cudaFuncSetAttribute(attn_mma_kernel, cudaFuncAttributeMaxDynamicSharedMemorySize, SMEM_TOTAL);
    dim3 grid(S_LEN / BQ, 16, 8);
    attn_mma_kernel<<<grid, THREADS, SMEM_TOTAL>>>(mem, qry, bias, sl, out);
}

// round 8
// speedup vs baseline: 1.8499x; 1.1690x over previous
#include <cuda_runtime.h>
#include <cuda_fp16.h>
#include <cstdint>

// FA2-style mma.sync FP16 flash attention (R8).
// 4 warps/CTA, 32 q-rows per warp: halves duplicated K/V ldmatrix traffic.
// Fused per-16-key-group S->exp->PV (no row reduction needed pre-PV).
// Q fragments hoisted across the whole key loop. K fp16 hi+lo (2-term QK),
// V fp16 single term. exp2 softmax, mask folded into bias. mean(V) for L==0.

#define S_LEN 1024
#define BQ 128
#define BK 64
#define THREADS 128
#define LOG2E 1.44269504f
#define C2 13.0f

#define OFF_Q   0u
#define BUF0    16384u
#define BUF1    40960u
#define KHI     0u
#define KLO     8192u
#define VHI     16384u
#define OFF_BIAS 65536u
#define SMEM_TOTAL 69632

static __device__ __forceinline__ uint32_t smem_u32(const void* p) {
    uint32_t a;
    asm("{ .reg .u64 t; cvta.to.shared.u64 t, %1; cvt.u32.u64 %0, t; }" : "=r"(a) : "l"(p));
    return a;
}
static __device__ __forceinline__ void ldsm4(uint32_t addr, uint32_t& r0, uint32_t& r1,
                                             uint32_t& r2, uint32_t& r3) {
    asm volatile("ldmatrix.sync.aligned.m8n8.x4.shared.b16 {%0,%1,%2,%3}, [%4];"
                 : "=r"(r0), "=r"(r1), "=r"(r2), "=r"(r3) : "r"(addr));
}
static __device__ __forceinline__ void ldsm4t(uint32_t addr, uint32_t& r0, uint32_t& r1,
                                              uint32_t& r2, uint32_t& r3) {
    asm volatile("ldmatrix.sync.aligned.m8n8.x4.trans.shared.b16 {%0,%1,%2,%3}, [%4];"
                 : "=r"(r0), "=r"(r1), "=r"(r2), "=r"(r3) : "r"(addr));
}
static __device__ __forceinline__ void mma16816(float* c, uint32_t a0, uint32_t a1,
                                                uint32_t a2, uint32_t a3,
                                                uint32_t b0, uint32_t b1) {
    asm volatile("mma.sync.aligned.m16n8k16.row.col.f32.f16.f16.f32 "
                 "{%0,%1,%2,%3}, {%4,%5,%6,%7}, {%8,%9}, {%0,%1,%2,%3};"
                 : "+f"(c[0]), "+f"(c[1]), "+f"(c[2]), "+f"(c[3])
                 : "r"(a0), "r"(a1), "r"(a2), "r"(a3), "r"(b0), "r"(b1));
}
// pack: x -> low half, y -> high half
static __device__ __forceinline__ uint32_t pack_f16(float x, float y) {
    uint32_t r;
    asm("cvt.rn.f16x2.f32 %0, %1, %2;" : "=r"(r) : "f"(y), "f"(x));
    return r;
}

// 64x64 fp32 tile load: 1024 float4s over 128 threads = 8 each
static __device__ __forceinline__ void ldg_tile(const float* base, int s0, int tid, float4* r) {
    #pragma unroll
    for (int i = 0; i < 8; i++) {
        int idx = tid + i * THREADS, row = idx >> 4, c4 = idx & 15;
        r[i] = *reinterpret_cast<const float4*>(base + (size_t)(s0 + row) * 2048 + c4 * 4);
    }
}
static __device__ __forceinline__ void sts_tile_k(char* sm, uint32_t hi_off, uint32_t lo_off,
                                                  int tid, const float4* r) {
    #pragma unroll
    for (int i = 0; i < 8; i++) {
        int idx = tid + i * THREADS, row = idx >> 4, c4 = idx & 15;
        uint32_t off = (uint32_t)(row * 128 + (((c4 >> 1) ^ (row & 7)) << 4) + ((c4 & 1) << 3));
        float x = r[i].x, y = r[i].y, z = r[i].z, w = r[i].w;
        __half hx = __float2half_rn(x), hy = __float2half_rn(y);
        __half hz = __float2half_rn(z), hw = __float2half_rn(w);
        __half2 p0 = __halves2half2(hx, hy), p1 = __halves2half2(hz, hw);
        uint2 hi = { *reinterpret_cast<uint32_t*>(&p0), *reinterpret_cast<uint32_t*>(&p1) };
        uint2 lo = { pack_f16(x - __half2float(hx), y - __half2float(hy)),
                     pack_f16(z - __half2float(hz), w - __half2float(hw)) };
        *reinterpret_cast<uint2*>(sm + hi_off + off) = hi;
        *reinterpret_cast<uint2*>(sm + lo_off + off) = lo;
    }
}
static __device__ __forceinline__ void sts_tile_v(char* sm, uint32_t v_off,
                                                  int tid, const float4* r) {
    #pragma unroll
    for (int i = 0; i < 8; i++) {
        int idx = tid + i * THREADS, row = idx >> 4, c4 = idx & 15;
        uint32_t off = (uint32_t)(row * 128 + (((c4 >> 1) ^ (row & 7)) << 4) + ((c4 & 1) << 3));
        uint2 hv = { pack_f16(r[i].x, r[i].y), pack_f16(r[i].z, r[i].w) };
        *reinterpret_cast<uint2*>(sm + v_off + off) = hv;
    }
}

__global__ void __launch_bounds__(THREADS, 2)
attn_mma_kernel(const float* __restrict__ mem, const float* __restrict__ qry,
                const float* __restrict__ bias, const int* __restrict__ seqlen,
                float* __restrict__ out)
{
    extern __shared__ char smem[];
    const uint32_t sb = smem_u32(smem);
    const int tid = threadIdx.x, lane = tid & 31, wid = tid >> 5;   // 4 warps
    const int qt = blockIdx.x, h = blockIdx.y, b = blockIdx.z;

    const int L = seqlen[b];
    const float* kbase = mem + (size_t)b * S_LEN * 2048 + h * 64;
    const float* vbase = kbase + 1024;
    float* obase0 = out + ((size_t)(b * S_LEN + qt * BQ)) * 1024 + h * 64;

    if (L == 0) {
        // softmax exactly uniform (fp32 rounding of -1e12): O = mean_k V
        float* red = reinterpret_cast<float*>(smem);
        int d = tid & 63, slc = tid >> 6;        // 2 slices of 512 keys
        float s = 0.f;
        #pragma unroll 4
        for (int k = slc * 512; k < slc * 512 + 512; k++)
            s += vbase[(size_t)k * 2048 + d];
        red[slc * 64 + d] = s;
        __syncthreads();
        if (tid < 64) red[128 + tid] = (red[tid] + red[64 + tid]) * (1.f / 1024.f);
        __syncthreads();
        #pragma unroll
        for (int r = 0; r < 16; r++) {
            int idx = tid + r * THREADS;
            int row = idx >> 4, c4 = idx & 15;
            float4 vv = *reinterpret_cast<const float4*>(&red[128 + c4 * 4]);
            *reinterpret_cast<float4*>(obase0 + (size_t)row * 1024 + c4 * 4) = vv;
        }
        return;
    }

    float* Bs = reinterpret_cast<float*>(smem + OFF_BIAS);
    #pragma unroll
    for (int i = tid; i < S_LEN; i += THREADS)
        Bs[i] = (i < L) ? bias[i] * LOG2E - C2 : -1e30f;

    // Q tile [128 x 64] scaled by (1/8)*log2e, fp16, swizzled
    const float* qbase = qry + ((size_t)(b * S_LEN + qt * BQ)) * 1024 + h * 64;
    #pragma unroll
    for (int r = 0; r < 16; r++) {
        int idx = tid + r * THREADS;
        int row = idx >> 4, c4 = idx & 15;
        float4 v = *reinterpret_cast<const float4*>(qbase + (size_t)row * 1024 + c4 * 4);
        const float sc = 0.125f * LOG2E;
        uint32_t off = (uint32_t)(row * 128 + (((c4 >> 1) ^ (row & 7)) << 4) + ((c4 & 1) << 3));
        uint2 q16 = { pack_f16(v.x * sc, v.y * sc), pack_f16(v.z * sc, v.w * sc) };
        *reinterpret_cast<uint2*>(smem + OFF_Q + off) = q16;
    }

    const int nt = (L + BK - 1) >> 6;

    // lane geometry
    const int s7 = lane & 7;
    const int qA = (lane & 7) + ((lane >> 3) & 1) * 8;
    const int qB = lane >> 4;
    const int kA = (lane & 7) + (lane >> 4) * 8;
    const int kB = (lane >> 3) & 1;

    float oacc[2][8][4];                 // [rowblock][d-col][frag]
    #pragma unroll
    for (int rb = 0; rb < 2; rb++)
        #pragma unroll
        for (int i = 0; i < 8; i++)
            #pragma unroll
            for (int j = 0; j < 4; j++) oacc[rb][i][j] = 0.f;
    float lsA[2] = {0.f, 0.f}, lsB[2] = {0.f, 0.f};   // per rb: rows r and r+8

    // prologue: tile 0 -> BUF0
    {
        float4 kreg[8], vreg[8];
        ldg_tile(kbase, 0, tid, kreg);
        ldg_tile(vbase, 0, tid, vreg);
        sts_tile_k(smem, BUF0 + KHI, BUF0 + KLO, tid, kreg);
        sts_tile_v(smem, BUF0 + VHI, tid, vreg);
    }
    __syncthreads();

    // hoist Q fragments for both 16-row blocks across the whole key loop
    uint32_t qf[4][2][4];
    #pragma unroll
    for (int kk = 0; kk < 4; kk++)
        #pragma unroll
        for (int rb = 0; rb < 2; rb++)
            ldsm4(sb + OFF_Q + (uint32_t)((32 * wid + 16 * rb + qA) * 128 +
                  (((2 * kk + qB) ^ s7) << 4)),
                  qf[kk][rb][0], qf[kk][rb][1], qf[kk][rb][2], qf[kk][rb][3]);

    for (int t = 0; t < nt; t++) {
        const int s0 = t * BK;
        const uint32_t kb = sb + ((t & 1) ? BUF1 : BUF0);
        const uint32_t nb = ((t + 1) & 1) ? BUF1 : BUF0;
        const bool hn = (t + 1 < nt);

        float4 kreg[8], vreg[8];
        if (hn) { ldg_tile(kbase, s0 + BK, tid, kreg); ldg_tile(vbase, s0 + BK, tid, vreg); }

        #pragma unroll
        for (int jj = 0; jj < 4; jj++) {          // 16-key group
            // ---- S = Q*Khi + Q*Klo for this key group ----
            float sacc[2][2][4];
            #pragma unroll
            for (int rb = 0; rb < 2; rb++)
                #pragma unroll
                for (int u = 0; u < 2; u++)
                    #pragma unroll
                    for (int j = 0; j < 4; j++) sacc[rb][u][j] = 0.f;

            #pragma unroll
            for (int kk = 0; kk < 4; kk++) {
                uint32_t kh0, kh1, kh2, kh3, kl0, kl1, kl2, kl3;
                uint32_t ak = kb + KHI + (uint32_t)((16 * jj + kA) * 128 +
                              (((2 * kk + kB) ^ s7) << 4));
                ldsm4(ak, kh0, kh1, kh2, kh3);
                ldsm4(ak + 8192, kl0, kl1, kl2, kl3);
                #pragma unroll
                for (int rb = 0; rb < 2; rb++) {
                    mma16816(sacc[rb][0], qf[kk][rb][0], qf[kk][rb][1], qf[kk][rb][2], qf[kk][rb][3], kh0, kh1);
                    mma16816(sacc[rb][1], qf[kk][rb][0], qf[kk][rb][1], qf[kk][rb][2], qf[kk][rb][3], kh2, kh3);
                    mma16816(sacc[rb][0], qf[kk][rb][0], qf[kk][rb][1], qf[kk][rb][2], qf[kk][rb][3], kl0, kl1);
                    mma16816(sacc[rb][1], qf[kk][rb][0], qf[kk][rb][1], qf[kk][rb][2], qf[kk][rb][3], kl2, kl3);
                }
            }

            // ---- exp2 (mask folded in Bs) -> P A-fragments ----
            uint32_t pa[2][4];
            #pragma unroll
            for (int u = 0; u < 2; u++) {
                int keyb = s0 + 16 * jj + 8 * u + 2 * (lane & 3);
                float2 bb = *reinterpret_cast<const float2*>(&Bs[keyb]);
                #pragma unroll
                for (int rb = 0; rb < 2; rb++) {
                    float p0 = exp2f(sacc[rb][u][0] + bb.x);
                    float p1 = exp2f(sacc[rb][u][1] + bb.y);
                    float p2 = exp2f(sacc[rb][u][2] + bb.x);
                    float p3 = exp2f(sacc[rb][u][3] + bb.y);
                    lsA[rb] += p0 + p1;
                    lsB[rb] += p2 + p3;
                    pa[rb][2 * u]     = pack_f16(p0, p1);
                    pa[rb][2 * u + 1] = pack_f16(p2, p3);
                }
            }

            // ---- O += P * V ----
            #pragma unroll
            for (int jn = 0; jn < 4; jn++) {
                uint32_t vh0, vh1, vh2, vh3;
                uint32_t av = kb + VHI + (uint32_t)((16 * jj + qA) * 128 +
                              (((2 * jn + qB) ^ s7) << 4));
                ldsm4t(av, vh0, vh1, vh2, vh3);
                #pragma unroll
                for (int rb = 0; rb < 2; rb++) {
                    mma16816(oacc[rb][2 * jn],     pa[rb][0], pa[rb][1], pa[rb][2], pa[rb][3], vh0, vh1);
                    mma16816(oacc[rb][2 * jn + 1], pa[rb][0], pa[rb][1], pa[rb][2], pa[rb][3], vh2, vh3);
                }
            }
        }

        if (hn) {
            sts_tile_k(smem, nb + KHI, nb + KLO, tid, kreg);
            sts_tile_v(smem, nb + VHI, tid, vreg);
        }
        __syncthreads();
    }

    // normalize within quads, store (each warp: rows 32*wid .. +31)
    #pragma unroll
    for (int rb = 0; rb < 2; rb++) {
        float a = lsA[rb], c = lsB[rb];
        a += __shfl_xor_sync(0xffffffffu, a, 1);
        a += __shfl_xor_sync(0xffffffffu, a, 2);
        c += __shfl_xor_sync(0xffffffffu, c, 1);
        c += __shfl_xor_sync(0xffffffffu, c, 2);
        float invA = 1.f / a, invB = 1.f / c;
        const int r = lane >> 2, c2 = (lane & 3) * 2;
        float* ob = obase0 + (size_t)(32 * wid + 16 * rb + r) * 1024;
        #pragma unroll
        for (int jd = 0; jd < 8; jd++) {
            float2 s0v = { oacc[rb][jd][0] * invA, oacc[rb][jd][1] * invA };
            float2 s1v = { oacc[rb][jd][2] * invB, oacc[rb][jd][3] * invB };
            *reinterpret_cast<float2*>(ob + 8 * jd + c2) = s0v;
            *reinterpret_cast<float2*>(ob + 8 * 1024 + 8 * jd + c2) = s1v;
        }
    }
}

extern "C" void kernel_launch(void* const* d_in, const int* in_sizes, int n_in,
                              void* d_out, int out_size) {
    const float* mem  = (const float*)d_in[0];   // [8,1024,2048]
    const float* qry  = (const float*)d_in[1];   // [8,1024,1024]
    const float* bias = (const float*)d_in[2];   // [1024]
    const int*   sl   = (const int*)d_in[3];     // [8,1]
    float* out = (float*)d_out;

    cudaFuncSetAttribute(attn_mma_kernel, cudaFuncAttributeMaxDynamicSharedMemorySize, SMEM_TOTAL);
    dim3 grid(S_LEN / BQ, 16, 8);
    attn_mma_kernel<<<grid, THREADS, SMEM_TOTAL>>>(mem, qry, bias, sl, out);
}